// round 6
// baseline (speedup 1.0000x reference)
#include <cuda_runtime.h>

// AttentionOptimizer: out = spins - LR*(grads + SMOOTH*g_smooth) + noise
// g_smooth = conv3(u)/conv3(v),  u = g*exp(-BETA*|g|), v = exp(-BETA*|g|),
// separable per-axis kernel w[d] = exp(-0.0125*(d*2/19)^2).
//
// R6: one kernel, CTA per (b, y_out), 800 threads. Phase 1 (y-reduction:
// LDG + expf + fma chain) is split in half across thread pairs. Phase 2
// (z-conv) is linear, so each half convolves ITS OWN partial plane — no
// duplicated work (R5's mistake). Phase 3 (x-conv) runs on the low half and
// folds the two partials together inside its loop.

#define LLAT 20
#define PLANE 400                 // LLAT*LLAT
#define NPTS 8000                 // LLAT^3
#define NTHR 800

// Packed f32x2 FMA (sm_103a): d = a*b + c on both lanes.
static __device__ __forceinline__ float2 fma2(float2 a, float2 b, float2 c) {
    float2 d;
    asm("fma.rn.f32x2 %0, %1, %2, %3;"
        : "=l"(*reinterpret_cast<unsigned long long*>(&d))
        : "l"(*reinterpret_cast<unsigned long long*>(&a)),
          "l"(*reinterpret_cast<unsigned long long*>(&b)),
          "l"(*reinterpret_cast<unsigned long long*>(&c)));
    return d;
}

static __device__ __forceinline__ float2 add2(float2 a, float2 b) {
    return make_float2(a.x + b.x, a.y + b.y);
}

__global__ void __launch_bounds__(NTHR, 1)
attn_opt_fused(const float* __restrict__ grads,
               const float* __restrict__ spins,
               const float* __restrict__ noise,
               float* __restrict__ out)
{
    __shared__ float2 Vp[2][PLANE];           // per-half y-partial planes
    __shared__ float2 Tp[2][PLANE];           // per-half z-conv of partials
    __shared__ float2 w2[2 * LLAT - 1];

    const int t  = threadIdx.x;
    const int h  = (t >= PLANE) ? 1 : 0;      // y-half
    const int tp = t - h * PLANE;             // tp = xp*20 + zp
    const int b  = blockIdx.x / LLAT;
    const int yo = blockIdx.x - b * LLAT;     // output y-plane
    const int xp = tp / LLAT;
    const int zp = tp - xp * LLAT;

    // Hoisted epilogue operands (h==0 writes the output).
    const int gi = b * NPTS + xp * PLANE + yo * LLAT + zp;
    float s_v = 0.0f, n_v = 0.0f, g_v = 0.0f;
    if (h == 0) { s_v = spins[gi]; n_v = noise[gi]; g_v = grads[gi]; }

    // Weight table: w[d] = exp(-0.0125*(d*2/19)^2), d in [-19,19], dup-packed.
    if (t < 2 * LLAT - 1) {
        const float d = (float)(t - (LLAT - 1)) * (2.0f / (float)(LLAT - 1));
        const float w = __expf(-0.0125f * d * d);
        w2[t] = make_float2(w, w);
    }

    // Phase 1 (split): partial y-reduction over 10 y' values per thread.
    const float* gcol = grads + b * NPTS + xp * PLANE + zp;
    float gc[LLAT / 2];
#pragma unroll
    for (int k = 0; k < LLAT / 2; k++)
        gc[k] = gcol[(h * (LLAT / 2) + k) * LLAT];

    __syncthreads();   // w2 ready

    float2 acc = make_float2(0.0f, 0.0f);
#pragma unroll
    for (int k = 0; k < LLAT / 2; k++) {
        const int yp = h * (LLAT / 2) + k;
        const float e = __expf(-2.0f * fabsf(gc[k]));
        const float2 ue = make_float2(gc[k] * e, e);
        acc = fma2(ue, w2[(LLAT - 1) + yo - yp], acc);   // broadcast LDS.64
    }
    Vp[h][tp] = acc;
    __syncthreads();

    // Phase 2: z-conv of each half's OWN partial plane (linear => no dup).
    acc = make_float2(0.0f, 0.0f);
#pragma unroll
    for (int j = 0; j < LLAT; j++)
        acc = fma2(Vp[h][xp * LLAT + j], w2[(LLAT - 1) + zp - j], acc);
    Tp[h][tp] = acc;
    __syncthreads();

    // Phase 3 (low half only): x-conv with the half-combine folded in.
    if (h == 0) {
        acc = make_float2(0.0f, 0.0f);
#pragma unroll
        for (int j = 0; j < LLAT; j++) {
            const float2 tj = add2(Tp[0][j * LLAT + zp], Tp[1][j * LLAT + zp]);
            acc = fma2(tj, w2[(LLAT - 1) + xp - j], acc);
        }
        // Epilogue: out = s - 0.05*g - 0.5*(u/v) + n
        out[gi] = s_v - 0.05f * g_v - 0.5f * __fdividef(acc.x, acc.y) + n_v;
    }
}

extern "C" void kernel_launch(void* const* d_in, const int* in_sizes, int n_in,
                              void* d_out, int out_size)
{
    const float* grads = (const float*)d_in[0];
    const float* spins = (const float*)d_in[1];
    // d_in[2] = pos: unused — lattice geometry is known analytically.
    const float* noise = (const float*)d_in[3];
    float* out = (float*)d_out;

    const int B = in_sizes[0] / NPTS;
    attn_opt_fused<<<B * LLAT, NTHR>>>(grads, spins, noise, out);
}

// round 7
// speedup vs baseline: 1.2963x; 1.2963x over previous
#include <cuda_runtime.h>

// AttentionOptimizer: out = spins - LR*(grads + SMOOTH*g_smooth) + noise
// g_smooth = conv3(u)/conv3(v),  u = g*exp(-BETA*|g|), v = exp(-BETA*|g|),
// separable per-axis kernel w[d] = exp(-0.0125*(d*2/19)^2) = exp(-0.05 d^2/361).
//
// R7 = R4 structure (one CTA per (b,y_out), 400 threads, one output/thread)
// with the weight table lifted to compile-time __constant__ data:
//  - phase 1 weight index (19 + yo - yp) is CTA-uniform -> LDCU broadcast,
//    so phase 1 runs with NO preceding barrier;
//  - phases 2/3 read weights from a smem copy (per-thread indices would
//    cause divergent constant-cache replays); the copy is covered by the
//    barrier that phase 2 needs anyway. 2 syncs total (was 3), no MUFU
//    table build.

#define LLAT 20
#define PLANE 400                 // LLAT*LLAT
#define NPTS 8000                 // LLAT^3

// CW2[i] = {w,w} with w = exp(-0.05*(i-19)^2/361)  (hand-evaluated)
__constant__ float2 CW2[2 * LLAT - 1] = {
    {0.9512294245f, 0.9512294245f}, {0.9561166621f, 0.9561166621f},
    {0.9607628249f, 0.9607628249f}, {0.9651641734f, 0.9651641734f},
    {0.9693171397f, 0.9693171397f}, {0.9732183487f, 0.9732183487f},
    {0.9768646216f, 0.9768646216f}, {0.9802529795f, 0.9802529795f},
    {0.9833806481f, 0.9833806481f}, {0.9862450604f, 0.9862450604f},
    {0.9888438596f, 0.9888438596f}, {0.9911749058f, 0.9911749058f},
    {0.9932362740f, 0.9932362740f}, {0.9950262606f, 0.9950262606f},
    {0.9965433840f, 0.9965433840f}, {0.9977863872f, 0.9977863872f},
    {0.9987542392f, 0.9987542392f}, {0.9994461368f, 0.9994461368f},
    {0.9998615054f, 0.9998615054f}, {1.0000000000f, 1.0000000000f},
    {0.9998615054f, 0.9998615054f}, {0.9994461368f, 0.9994461368f},
    {0.9987542392f, 0.9987542392f}, {0.9977863872f, 0.9977863872f},
    {0.9965433840f, 0.9965433840f}, {0.9950262606f, 0.9950262606f},
    {0.9932362740f, 0.9932362740f}, {0.9911749058f, 0.9911749058f},
    {0.9888438596f, 0.9888438596f}, {0.9862450604f, 0.9862450604f},
    {0.9833806481f, 0.9833806481f}, {0.9802529795f, 0.9802529795f},
    {0.9768646216f, 0.9768646216f}, {0.9732183487f, 0.9732183487f},
    {0.9693171397f, 0.9693171397f}, {0.9651641734f, 0.9651641734f},
    {0.9607628249f, 0.9607628249f}, {0.9561166621f, 0.9561166621f},
    {0.9512294245f, 0.9512294245f}
};

// Packed f32x2 FMA (sm_103a): d = a*b + c on both lanes.
static __device__ __forceinline__ float2 fma2(float2 a, float2 b, float2 c) {
    float2 d;
    asm("fma.rn.f32x2 %0, %1, %2, %3;"
        : "=l"(*reinterpret_cast<unsigned long long*>(&d))
        : "l"(*reinterpret_cast<unsigned long long*>(&a)),
          "l"(*reinterpret_cast<unsigned long long*>(&b)),
          "l"(*reinterpret_cast<unsigned long long*>(&c)));
    return d;
}

__global__ void __launch_bounds__(PLANE, 1)
attn_opt_fused(const float* __restrict__ grads,
               const float* __restrict__ spins,
               const float* __restrict__ noise,
               float* __restrict__ out)
{
    __shared__ float2 V[PLANE];
    __shared__ float2 T[PLANE];
    __shared__ float2 w2[2 * LLAT - 1];   // smem copy for per-thread indices

    const int t  = threadIdx.x;              // t = xp*20 + zp
    const int b  = blockIdx.x / LLAT;
    const int yo = blockIdx.x - b * LLAT;    // output y-plane
    const int xp = t / LLAT;
    const int zp = t - xp * LLAT;

    // Hoisted epilogue operands: DRAM latency hides under the conv chain.
    const int gi = b * NPTS + xp * PLANE + yo * LLAT + zp;
    const float s_v = spins[gi];
    const float n_v = noise[gi];
    const float g_v = grads[gi];

    // Copy weight table to smem for phases 2/3 (divergent indices there).
    if (t < 2 * LLAT - 1) w2[t] = CW2[t];

    // Phase 1: y-reduction, weights via UNIFORM constant loads (no barrier).
    const float* gcol = grads + b * NPTS + xp * PLANE + zp;
    float gc[LLAT];
#pragma unroll
    for (int yp = 0; yp < LLAT; yp++) gc[yp] = gcol[yp * LLAT];

    float2 acc = make_float2(0.0f, 0.0f);
#pragma unroll
    for (int yp = 0; yp < LLAT; yp++) {
        const float e = __expf(-2.0f * fabsf(gc[yp]));
        const float2 ue = make_float2(gc[yp] * e, e);
        acc = fma2(ue, CW2[(LLAT - 1) + yo - yp], acc);   // uniform LDCU
    }
    V[t] = acc;
    __syncthreads();   // covers V and the w2 copy

    // Phase 2: z-conv. T[xp][zp] = sum_j w[zp-j] V[xp][j]
    acc = make_float2(0.0f, 0.0f);
#pragma unroll
    for (int j = 0; j < LLAT; j++)
        acc = fma2(V[xp * LLAT + j], w2[(LLAT - 1) + zp - j], acc);
    T[t] = acc;
    __syncthreads();

    // Phase 3: x-conv. R[xp][zp] = sum_j w[xp-j] T[j][zp]
    acc = make_float2(0.0f, 0.0f);
#pragma unroll
    for (int j = 0; j < LLAT; j++)
        acc = fma2(T[j * LLAT + zp], w2[(LLAT - 1) + xp - j], acc);

    // Epilogue: out = s - 0.05*g - 0.5*(u/v) + n
    out[gi] = s_v - 0.05f * g_v - 0.5f * __fdividef(acc.x, acc.y) + n_v;
}

extern "C" void kernel_launch(void* const* d_in, const int* in_sizes, int n_in,
                              void* d_out, int out_size)
{
    const float* grads = (const float*)d_in[0];
    const float* spins = (const float*)d_in[1];
    // d_in[2] = pos: unused — lattice geometry is known analytically.
    const float* noise = (const float*)d_in[3];
    float* out = (float*)d_out;

    const int B = in_sizes[0] / NPTS;
    attn_opt_fused<<<B * LLAT, PLANE>>>(grads, spins, noise, out);
}

// round 8
// speedup vs baseline: 1.3397x; 1.0335x over previous
#include <cuda_runtime.h>

// AttentionOptimizer: out = spins - LR*(grads + SMOOTH*g_smooth) + noise
// g_smooth = conv3(u)/conv3(v),  u = g*exp(-BETA*|g|), v = exp(-BETA*|g|),
// separable per-axis kernel w[d] = exp(-0.0125*(d*2/19)^2) = exp(-0.05 d^2/361).
//
// R8 = R7 (one CTA per (b,y_out), 400 threads, constant weights, 2 syncs)
// + critical-path shaves:
//   - gc column LDGs issued first (head of dependency chain)
//   - exp(-2|g|) folded to a single FMUL+EX2 via exp2f
//   - dual accumulators in every phase (halve dependent fma2 chains)
//   - 2-D grid (yo, b): no blockIdx division

#define LLAT 20
#define PLANE 400                 // LLAT*LLAT
#define NPTS 8000                 // LLAT^3
#define NEG2_LOG2E 2.8853900817779268f   // 2*log2(e)

// CW2[i] = {w,w} with w = exp(-0.05*(i-19)^2/361)  (hand-evaluated)
__constant__ float2 CW2[2 * LLAT - 1] = {
    {0.9512294245f, 0.9512294245f}, {0.9561166621f, 0.9561166621f},
    {0.9607628249f, 0.9607628249f}, {0.9651641734f, 0.9651641734f},
    {0.9693171397f, 0.9693171397f}, {0.9732183487f, 0.9732183487f},
    {0.9768646216f, 0.9768646216f}, {0.9802529795f, 0.9802529795f},
    {0.9833806481f, 0.9833806481f}, {0.9862450604f, 0.9862450604f},
    {0.9888438596f, 0.9888438596f}, {0.9911749058f, 0.9911749058f},
    {0.9932362740f, 0.9932362740f}, {0.9950262606f, 0.9950262606f},
    {0.9965433840f, 0.9965433840f}, {0.9977863872f, 0.9977863872f},
    {0.9987542392f, 0.9987542392f}, {0.9994461368f, 0.9994461368f},
    {0.9998615054f, 0.9998615054f}, {1.0000000000f, 1.0000000000f},
    {0.9998615054f, 0.9998615054f}, {0.9994461368f, 0.9994461368f},
    {0.9987542392f, 0.9987542392f}, {0.9977863872f, 0.9977863872f},
    {0.9965433840f, 0.9965433840f}, {0.9950262606f, 0.9950262606f},
    {0.9932362740f, 0.9932362740f}, {0.9911749058f, 0.9911749058f},
    {0.9888438596f, 0.9888438596f}, {0.9862450604f, 0.9862450604f},
    {0.9833806481f, 0.9833806481f}, {0.9802529795f, 0.9802529795f},
    {0.9768646216f, 0.9768646216f}, {0.9732183487f, 0.9732183487f},
    {0.9693171397f, 0.9693171397f}, {0.9651641734f, 0.9651641734f},
    {0.9607628249f, 0.9607628249f}, {0.9561166621f, 0.9561166621f},
    {0.9512294245f, 0.9512294245f}
};

// Packed f32x2 FMA (sm_103a): d = a*b + c on both lanes.
static __device__ __forceinline__ float2 fma2(float2 a, float2 b, float2 c) {
    float2 d;
    asm("fma.rn.f32x2 %0, %1, %2, %3;"
        : "=l"(*reinterpret_cast<unsigned long long*>(&d))
        : "l"(*reinterpret_cast<unsigned long long*>(&a)),
          "l"(*reinterpret_cast<unsigned long long*>(&b)),
          "l"(*reinterpret_cast<unsigned long long*>(&c)));
    return d;
}

static __device__ __forceinline__ float2 add2(float2 a, float2 b) {
    return make_float2(a.x + b.x, a.y + b.y);
}

__global__ void __launch_bounds__(PLANE, 1)
attn_opt_fused(const float* __restrict__ grads,
               const float* __restrict__ spins,
               const float* __restrict__ noise,
               float* __restrict__ out)
{
    __shared__ float2 V[PLANE];
    __shared__ float2 T[PLANE];
    __shared__ float2 w2[2 * LLAT - 1];   // smem copy for per-thread indices

    const int t  = threadIdx.x;              // t = xp*20 + zp
    const int yo = blockIdx.x;               // output y-plane
    const int b  = blockIdx.y;
    const int xp = t / LLAT;
    const int zp = t - xp * LLAT;

    // Head of the dependency chain: the 20-deep y-column of grads.
    const float* gcol = grads + b * NPTS + xp * PLANE + zp;
    float gc[LLAT];
#pragma unroll
    for (int yp = 0; yp < LLAT; yp++) gc[yp] = gcol[yp * LLAT];

    // Epilogue operands (needed only at the very end; latency fully hidden).
    const int gi = b * NPTS + xp * PLANE + yo * LLAT + zp;
    const float s_v = spins[gi];
    const float n_v = noise[gi];
    const float g_v = grads[gi];

    // Copy weight table to smem for phases 2/3 (divergent indices there).
    if (t < 2 * LLAT - 1) w2[t] = CW2[t];

    // Phase 1: y-reduction, weights via UNIFORM constant loads (no barrier).
    float2 a0 = make_float2(0.0f, 0.0f), a1 = make_float2(0.0f, 0.0f);
#pragma unroll
    for (int yp = 0; yp < LLAT; yp += 2) {
        const float e0 = exp2f(-NEG2_LOG2E * fabsf(gc[yp]));
        const float e1 = exp2f(-NEG2_LOG2E * fabsf(gc[yp + 1]));
        a0 = fma2(make_float2(gc[yp] * e0, e0),
                  CW2[(LLAT - 1) + yo - yp], a0);           // uniform LDCU
        a1 = fma2(make_float2(gc[yp + 1] * e1, e1),
                  CW2[(LLAT - 1) + yo - (yp + 1)], a1);
    }
    V[t] = add2(a0, a1);
    __syncthreads();   // covers V and the w2 copy

    // Phase 2: z-conv. T[xp][zp] = sum_j w[zp-j] V[xp][j]
    a0 = make_float2(0.0f, 0.0f); a1 = make_float2(0.0f, 0.0f);
#pragma unroll
    for (int j = 0; j < LLAT; j += 2) {
        a0 = fma2(V[xp * LLAT + j],     w2[(LLAT - 1) + zp - j],       a0);
        a1 = fma2(V[xp * LLAT + j + 1], w2[(LLAT - 1) + zp - (j + 1)], a1);
    }
    T[t] = add2(a0, a1);
    __syncthreads();

    // Phase 3: x-conv. R[xp][zp] = sum_j w[xp-j] T[j][zp]
    a0 = make_float2(0.0f, 0.0f); a1 = make_float2(0.0f, 0.0f);
#pragma unroll
    for (int j = 0; j < LLAT; j += 2) {
        a0 = fma2(T[j * LLAT + zp],       w2[(LLAT - 1) + xp - j],       a0);
        a1 = fma2(T[(j + 1) * LLAT + zp], w2[(LLAT - 1) + xp - (j + 1)], a1);
    }
    const float2 r = add2(a0, a1);

    // Epilogue: out = s - 0.05*g - 0.5*(u/v) + n
    out[gi] = s_v - 0.05f * g_v - 0.5f * __fdividef(r.x, r.y) + n_v;
}

extern "C" void kernel_launch(void* const* d_in, const int* in_sizes, int n_in,
                              void* d_out, int out_size)
{
    const float* grads = (const float*)d_in[0];
    const float* spins = (const float*)d_in[1];
    // d_in[2] = pos: unused — lattice geometry is known analytically.
    const float* noise = (const float*)d_in[3];
    float* out = (float*)d_out;

    const int B = in_sizes[0] / NPTS;
    dim3 grid(LLAT, B);
    attn_opt_fused<<<grid, PLANE>>>(grads, spins, noise, out);
}